// round 6
// baseline (speedup 1.0000x reference)
#include <cuda_runtime.h>
#include <math.h>

#define BATCH   64
#define NLEN    1500
#define NFREQ   1251
#define FCHUNK  64
#define NCHUNKS ((NFREQ + FCHUNK - 1) / FCHUNK)   // 20
#define SEG     8
#define SEGLEN  188                                // 8*188 = 1504 >= 1500
#define NPAD    (SEG * SEGLEN)                     // 1504
#define SEGU2   (SEGLEN / 2)                       // 94 ulonglong2 per segment

__device__ float        g_psd[BATCH * NFREQ];
__device__ float        g_per[BATCH];
__device__ unsigned int g_ticket;                  // zero-init; self-resetting

// ---- packed f32x2 helpers (sm_103a) ----
__device__ __forceinline__ unsigned long long pk2(float lo, float hi) {
    unsigned long long r;
    asm("mov.b64 %0, {%1, %2};" : "=l"(r) : "f"(lo), "f"(hi));
    return r;
}
__device__ __forceinline__ void upk2(unsigned long long v, float& lo, float& hi) {
    asm("mov.b64 {%0, %1}, %2;" : "=f"(lo), "=f"(hi) : "l"(v));
}
__device__ __forceinline__ unsigned long long fma2(unsigned long long a,
                                                   unsigned long long b,
                                                   unsigned long long c) {
    unsigned long long d;
    asm("fma.rn.f32x2 %0, %1, %2, %3;" : "=l"(d) : "l"(a), "l"(b), "l"(c));
    return d;
}

// Frequency grid value, matching jnp.arange semantics: iota*step + start in f32
__device__ __forceinline__ float grid_f(int i) {
    return __fadd_rn(__fmul_rn((float)i, 0.002f), 0.5f);
}

// ============================================================================
// Kernel 1: segmented Goertzel PSD with 2 independent chains per thread.
// Block = (batch pair, 64-freq chunk), 256 threads = 64 freq lanes x 4
// segment-pairs. Each thread runs TWO 188-step Goertzel recurrences (ILP=2
// breaks the 4-cycle RAW chain: one warp can saturate the SMSP fma pipe),
// both batches of the pair packed in f32x2. Partial spectra are rotated and
// reduced in SMEM (reduction buffer overlaid on the dead x buffer).
// ============================================================================
__global__ void __launch_bounds__(256)
goertzel_kernel(const float* __restrict__ x, const float* __restrict__ fs)
{
    __shared__ __align__(16) char smem_raw[(NPAD / 2) * 16];   // 12032 B
    ulonglong2* sx2 = (ulonglong2*)smem_raw;
    float4*     red = (float4*)smem_raw;    // overlaid AFTER sx2 is dead

    const int tid = threadIdx.x;
    const int bp  = blockIdx.y;             // batch pair 0..31
    const int b0  = 2 * bp;
    const int b1  = 2 * bp + 1;

    // issue fs loads + trig early (overlap MUFU with x loads)
    const int fl  = tid & (FCHUNK - 1);     // frequency lane 0..63
    const int sp  = tid >> 6;               // segment pair 0..3
    const int f   = blockIdx.x * FCHUNK + fl;
    const int fc  = (f < NFREQ) ? f : (NFREQ - 1);
    const float fval = grid_f(fc);

    const float TWO_PI = 6.283185307179586476925f;
    const float w0 = TWO_PI * fval / fs[b0];
    const float w1 = TWO_PI * fval / fs[b1];
    float c0, sn0, c1, sn1;
    sincosf(w0, &sn0, &c0);
    sincosf(w1, &sn1, &c1);

    // rotation angles for the two chains: phi = -w * (n0 + SEGLEN - 1)
    const float nrotA = (float)((2 * sp)     * SEGLEN + SEGLEN - 1);
    const float nrotB = (float)((2 * sp + 1) * SEGLEN + SEGLEN - 1);
    float rcA0, rsA0, rcA1, rsA1, rcB0, rsB0, rcB1, rsB1;
    sincosf(-w0 * nrotA, &rsA0, &rcA0);
    sincosf(-w1 * nrotA, &rsA1, &rcA1);
    sincosf(-w0 * nrotB, &rsB0, &rcB0);
    sincosf(-w1 * nrotB, &rsB1, &rcB1);

    // ---- load & pack x: 2 samples per ulonglong2 entry ----
    const float2* __restrict__ x0v = (const float2*)(x + b0 * NLEN);
    const float2* __restrict__ x1v = (const float2*)(x + b1 * NLEN);
    for (int i = tid; i < NLEN / 2; i += 256) {
        const float2 a = x0v[i];
        const float2 b = x1v[i];
        ulonglong2 v;
        v.x = pk2(a.x, b.x);
        v.y = pk2(a.y, b.y);
        sx2[i] = v;
    }
    if (tid < (NPAD - NLEN) / 2) {          // zero-pad entries 750,751
        ulonglong2 z; z.x = 0ull; z.y = 0ull;
        sx2[NLEN / 2 + tid] = z;
    }
    __syncthreads();

    const unsigned long long coeff = pk2(2.0f * c0, 2.0f * c1);
    const unsigned long long NEG1  = pk2(-1.0f, -1.0f);
    unsigned long long s1A = 0ull, s2A = 0ull;
    unsigned long long s1B = 0ull, s2B = 0ull;

    const ulonglong2* __restrict__ pA = sx2 + (2 * sp) * SEGU2;
    const ulonglong2* __restrict__ pB = pA + SEGU2;

    #pragma unroll 2
    for (int i = 0; i < SEGU2; i++) {
        const ulonglong2 vA = pA[i];
        const ulonglong2 vB = pB[i];
        unsigned long long t, s;
        // interleave the two independent chains (ILP=2)
        t = fma2(s2A, NEG1, vA.x);  s = fma2(coeff, s1A, t);  s2A = s1A; s1A = s;
        t = fma2(s2B, NEG1, vB.x);  s = fma2(coeff, s1B, t);  s2B = s1B; s1B = s;
        t = fma2(s2A, NEG1, vA.y);  s = fma2(coeff, s1A, t);  s2A = s1A; s1A = s;
        t = fma2(s2B, NEG1, vB.y);  s = fma2(coeff, s1B, t);  s2B = s1B; s1B = s;
    }

    // ---- epilogue: P = (s1 - c*s2) + j(sin*s2), rotated, chains summed ----
    float aA0, aA1, dA0, dA1, aB0, aB1, dB0, dB1;
    upk2(s1A, aA0, aA1); upk2(s2A, dA0, dA1);
    upk2(s1B, aB0, aB1); upk2(s2B, dB0, dB1);

    const float greA0 = aA0 - c0 * dA0, gimA0 = sn0 * dA0;
    const float greA1 = aA1 - c1 * dA1, gimA1 = sn1 * dA1;
    const float greB0 = aB0 - c0 * dB0, gimB0 = sn0 * dB0;
    const float greB1 = aB1 - c1 * dB1, gimB1 = sn1 * dB1;

    float4 r;
    r.x = (rcA0 * greA0 - rsA0 * gimA0) + (rcB0 * greB0 - rsB0 * gimB0);  // b0 Re
    r.y = (rcA0 * gimA0 + rsA0 * greA0) + (rcB0 * gimB0 + rsB0 * greB0);  // b0 Im
    r.z = (rcA1 * greA1 - rsA1 * gimA1) + (rcB1 * greB1 - rsB1 * gimB1);  // b1 Re
    r.w = (rcA1 * gimA1 + rsA1 * greA1) + (rcB1 * gimB1 + rsB1 * greB1);  // b1 Im

    __syncthreads();                        // sx2 dead from here; red takes over
    if (sp > 0) red[(sp - 1) * FCHUNK + fl] = r;
    __syncthreads();

    if (sp == 0 && f < NFREQ) {
        #pragma unroll
        for (int s = 0; s < 3; s++) {
            const float4 o = red[s * FCHUNK + fl];
            r.x += o.x; r.y += o.y; r.z += o.z; r.w += o.w;
        }
        g_psd[b0 * NFREQ + f] = r.x * r.x + r.y * r.y;
        g_psd[b1 * NFREQ + f] = r.z * r.z + r.w * r.w;
    }
}

// ============================================================================
// Kernel 2: per-batch single-pass online log-softmax at argmin-|f-f_true|,
// with the batch mean fused via a self-resetting last-block ticket.
// ============================================================================
__global__ void __launch_bounds__(256)
reduce_kernel(const float* __restrict__ f_true, float* __restrict__ out)
{
    const int b   = blockIdx.x;
    const int tid = threadIdx.x;
    const float* __restrict__ psd = g_psd + b * NFREQ;

    __shared__ float sm[8], ss[8], sbd[8];
    __shared__ int   sbi[8];

    const float ft = f_true[b];

    // ---- single pass: online softmax (m, s) + argmin ----
    float m  = -1e30f;
    float se = 0.0f;
    float bd = 1e30f;
    int   bi = NFREQ;
    for (int f = tid; f < NFREQ; f += 256) {
        const float v = psd[f];
        if (v > m) { se = se * expf(m - v) + 1.0f; m = v; }
        else       { se += expf(v - m); }
        const float d = fabsf(grid_f(f) - ft);
        if (d < bd) { bd = d; bi = f; }     // strict <: first occurrence/lane
    }
    #pragma unroll
    for (int o = 16; o > 0; o >>= 1) {
        const float om = __shfl_down_sync(0xffffffffu, m, o);
        const float os = __shfl_down_sync(0xffffffffu, se, o);
        const float M  = fmaxf(m, om);
        se = se * expf(m - M) + os * expf(om - M);
        m  = M;
        const float od = __shfl_down_sync(0xffffffffu, bd, o);
        const int   oi = __shfl_down_sync(0xffffffffu, bi, o);
        if (od < bd || (od == bd && oi < bi)) { bd = od; bi = oi; }
    }
    if ((tid & 31) == 0) {
        const int w = tid >> 5;
        sm[w] = m; ss[w] = se; sbd[w] = bd; sbi[w] = bi;
    }
    __syncthreads();

    if (tid == 0) {
        float M = sm[0];
        #pragma unroll
        for (int w = 1; w < 8; w++) M = fmaxf(M, sm[w]);
        float S = 0.0f, fbd = 1e30f;
        int   fbi = NFREQ;
        #pragma unroll
        for (int w = 0; w < 8; w++) {
            S += ss[w] * expf(sm[w] - M);
            if (sbd[w] < fbd || (sbd[w] == fbd && sbi[w] < fbi)) {
                fbd = sbd[w]; fbi = sbi[w];
            }
        }
        const float p = expf(psd[fbi] - M) / S;    // softmax[idx]
        g_per[b] = -logf(p + 1e-8f);

        // ---- fused mean: last block sums all per-sample losses ----
        __threadfence();
        const unsigned int t = atomicAdd(&g_ticket, 1u);
        if (t == BATCH - 1) {
            __threadfence();
            volatile float* gp = g_per;
            float tot = 0.0f;
            #pragma unroll
            for (int i = 0; i < BATCH; i++) tot += gp[i];
            out[0] = tot * (1.0f / (float)BATCH);
            g_ticket = 0;                   // self-reset: graph-replay safe
        }
    }
}

// ============================================================================
extern "C" void kernel_launch(void* const* d_in, const int* in_sizes, int n_in,
                              void* d_out, int out_size)
{
    const float* x      = (const float*)d_in[0];   // [64, 1500]
    const float* f_true = (const float*)d_in[1];   // [64]
    const float* fs     = (const float*)d_in[2];   // [64]
    float* out = (float*)d_out;                    // scalar

    dim3 g1(NCHUNKS, BATCH / 2);                   // (20, 32)
    goertzel_kernel<<<g1, 256>>>(x, fs);
    reduce_kernel<<<BATCH, 256>>>(f_true, out);
}

// round 7
// speedup vs baseline: 1.1745x; 1.1745x over previous
#include <cuda_runtime.h>
#include <math.h>

#define BATCH    64
#define NLEN     1500
#define NFREQ    1251
#define NFREQ_P  1252                               // padded row (16B-aligned rows)
#define FCHUNK   64
#define NCHUNKS  ((NFREQ + FCHUNK - 1) / FCHUNK)    // 20
#define SEG      8
#define SEGLEN   188                                // 8*188 = 1504 >= 1500
#define NPAD     (SEG * SEGLEN)                     // 1504
#define SEGU2    (SEGLEN / 2)                       // 94 ulonglong2 per segment

__device__ float        g_psd[BATCH * NFREQ_P];
__device__ float        g_per[BATCH];
__device__ unsigned int g_ticket;                   // zero-init; self-resetting

// ---- packed f32x2 helpers (sm_103a) ----
__device__ __forceinline__ unsigned long long pk2(float lo, float hi) {
    unsigned long long r;
    asm("mov.b64 %0, {%1, %2};" : "=l"(r) : "f"(lo), "f"(hi));
    return r;
}
__device__ __forceinline__ void upk2(unsigned long long v, float& lo, float& hi) {
    asm("mov.b64 {%0, %1}, %2;" : "=f"(lo), "=f"(hi) : "l"(v));
}
__device__ __forceinline__ unsigned long long fma2(unsigned long long a,
                                                   unsigned long long b,
                                                   unsigned long long c) {
    unsigned long long d;
    asm("fma.rn.f32x2 %0, %1, %2, %3;" : "=l"(d) : "l"(a), "l"(b), "l"(c));
    return d;
}

// Frequency grid value, matching jnp.arange semantics: iota*step + start in f32
__device__ __forceinline__ float grid_f(int i) {
    return __fadd_rn(__fmul_rn((float)i, 0.002f), 0.5f);
}

// ============================================================================
// Kernel 1: segmented Goertzel PSD, 2 independent chains/thread (ILP=2) and
// explicit register prefetch of the next SMEM pair (the R5/R6 limiter was the
// exposed 29-cycle LDS latency per iteration, not the fma pipe).
// Block = (batch pair, 64-freq chunk), 256 threads = 64 freq lanes x 4
// segment-pairs; both batches of the pair packed in f32x2 lanes.
// ============================================================================
__global__ void __launch_bounds__(256)
goertzel_kernel(const float* __restrict__ x, const float* __restrict__ fs)
{
    // +2 spare entries: tail prefetch may read one element past the last segment
    __shared__ __align__(16) char smem_raw[(NPAD / 2 + 2) * 16];
    ulonglong2* sx2 = (ulonglong2*)smem_raw;
    float4*     red = (float4*)smem_raw;     // overlaid AFTER sx2 is dead

    const int tid = threadIdx.x;
    const int bp  = blockIdx.y;              // batch pair 0..31
    const int b0  = 2 * bp;
    const int b1  = 2 * bp + 1;

    const int fl  = tid & (FCHUNK - 1);      // frequency lane 0..63
    const int sp  = tid >> 6;                // segment pair 0..3
    const int f   = blockIdx.x * FCHUNK + fl;
    const int fc  = (f < NFREQ) ? f : (NFREQ - 1);
    const float fval = grid_f(fc);

    const float TWO_PI = 6.283185307179586476925f;
    const float w0 = TWO_PI * fval / fs[b0];
    const float w1 = TWO_PI * fval / fs[b1];
    float c0, sn0, c1, sn1;
    sincosf(w0, &sn0, &c0);
    sincosf(w1, &sn1, &c1);

    // rotation angles for the two chains: phi = -w * (n0 + SEGLEN - 1)
    const float nrotA = (float)((2 * sp)     * SEGLEN + SEGLEN - 1);
    const float nrotB = (float)((2 * sp + 1) * SEGLEN + SEGLEN - 1);
    float rcA0, rsA0, rcA1, rsA1, rcB0, rsB0, rcB1, rsB1;
    sincosf(-w0 * nrotA, &rsA0, &rcA0);
    sincosf(-w1 * nrotA, &rsA1, &rcA1);
    sincosf(-w0 * nrotB, &rsB0, &rcB0);
    sincosf(-w1 * nrotB, &rsB1, &rcB1);

    // ---- load & pack x: 2 samples per ulonglong2 entry ----
    const float2* __restrict__ x0v = (const float2*)(x + b0 * NLEN);
    const float2* __restrict__ x1v = (const float2*)(x + b1 * NLEN);
    for (int i = tid; i < NLEN / 2; i += 256) {
        const float2 a = x0v[i];
        const float2 b = x1v[i];
        ulonglong2 v;
        v.x = pk2(a.x, b.x);
        v.y = pk2(a.y, b.y);
        sx2[i] = v;
    }
    if (tid < (NPAD - NLEN) / 2 + 2) {       // zero-pad 750,751 + 2 spares
        ulonglong2 z; z.x = 0ull; z.y = 0ull;
        sx2[NLEN / 2 + tid] = z;
    }
    __syncthreads();

    const unsigned long long coeff = pk2(2.0f * c0, 2.0f * c1);
    const unsigned long long NEG1  = pk2(-1.0f, -1.0f);
    unsigned long long s1A = 0ull, s2A = 0ull;
    unsigned long long s1B = 0ull, s2B = 0ull;

    const ulonglong2* __restrict__ pA = sx2 + (2 * sp) * SEGU2;
    const ulonglong2* __restrict__ pB = pA + SEGU2;

    // software-pipelined main loop: prefetch i+1 while computing on i
    ulonglong2 vA = pA[0];
    ulonglong2 vB = pB[0];
    #pragma unroll 2
    for (int i = 0; i < SEGU2; i++) {
        const ulonglong2 nA = pA[i + 1];     // spare slot makes tail read safe
        const ulonglong2 nB = pB[i + 1];
        unsigned long long t, s;
        // two independent Goertzel chains, interleaved (ILP=2)
        t = fma2(s2A, NEG1, vA.x);  s = fma2(coeff, s1A, t);  s2A = s1A; s1A = s;
        t = fma2(s2B, NEG1, vB.x);  s = fma2(coeff, s1B, t);  s2B = s1B; s1B = s;
        t = fma2(s2A, NEG1, vA.y);  s = fma2(coeff, s1A, t);  s2A = s1A; s1A = s;
        t = fma2(s2B, NEG1, vB.y);  s = fma2(coeff, s1B, t);  s2B = s1B; s1B = s;
        vA = nA;
        vB = nB;
    }

    // ---- epilogue: P = (s1 - c*s2) + j(sin*s2), rotated, chains summed ----
    float aA0, aA1, dA0, dA1, aB0, aB1, dB0, dB1;
    upk2(s1A, aA0, aA1); upk2(s2A, dA0, dA1);
    upk2(s1B, aB0, aB1); upk2(s2B, dB0, dB1);

    const float greA0 = aA0 - c0 * dA0, gimA0 = sn0 * dA0;
    const float greA1 = aA1 - c1 * dA1, gimA1 = sn1 * dA1;
    const float greB0 = aB0 - c0 * dB0, gimB0 = sn0 * dB0;
    const float greB1 = aB1 - c1 * dB1, gimB1 = sn1 * dB1;

    float4 r;
    r.x = (rcA0 * greA0 - rsA0 * gimA0) + (rcB0 * greB0 - rsB0 * gimB0);  // b0 Re
    r.y = (rcA0 * gimA0 + rsA0 * greA0) + (rcB0 * gimB0 + rsB0 * greB0);  // b0 Im
    r.z = (rcA1 * greA1 - rsA1 * gimA1) + (rcB1 * greB1 - rsB1 * gimB1);  // b1 Re
    r.w = (rcA1 * gimA1 + rsA1 * greA1) + (rcB1 * gimB1 + rsB1 * greB1);  // b1 Im

    __syncthreads();                         // sx2 dead; red overlay takes over
    if (sp > 0) red[(sp - 1) * FCHUNK + fl] = r;
    __syncthreads();

    if (sp == 0 && f < NFREQ) {
        #pragma unroll
        for (int s = 0; s < 3; s++) {
            const float4 o = red[s * FCHUNK + fl];
            r.x += o.x; r.y += o.y; r.z += o.z; r.w += o.w;
        }
        g_psd[b0 * NFREQ_P + f] = r.x * r.x + r.y * r.y;
        g_psd[b1 * NFREQ_P + f] = r.z * r.z + r.w * r.w;
    }
}

// ============================================================================
// Kernel 2: per-batch log-softmax at argmin-|f-f_true|, psd staged in SMEM
// (two cheap SMEM passes instead of latency-bound global passes), with the
// batch mean fused via a self-resetting last-block ticket.
// ============================================================================
__global__ void __launch_bounds__(256)
reduce_kernel(const float* __restrict__ f_true, float* __restrict__ out)
{
    __shared__ __align__(16) float spsd[NFREQ_P];   // 5008 B
    __shared__ float sred[8];
    __shared__ int   sidx[8];
    __shared__ int   sticket;
    __shared__ float sM;

    const int b   = blockIdx.x;
    const int tid = threadIdx.x;

    // ---- stage psd row into SMEM (313 float4 loads, high MLP) ----
    {
        const float4* __restrict__ src = (const float4*)(g_psd + b * NFREQ_P);
        float4* dst = (float4*)spsd;
        for (int i = tid; i < NFREQ_P / 4; i += 256)
            dst[i] = src[i];
    }
    __syncthreads();

    // ---- pass 1: max ----
    float m = -1e30f;
    for (int f = tid; f < NFREQ; f += 256)
        m = fmaxf(m, spsd[f]);
    #pragma unroll
    for (int o = 16; o > 0; o >>= 1)
        m = fmaxf(m, __shfl_down_sync(0xffffffffu, m, o));
    if ((tid & 31) == 0) sred[tid >> 5] = m;
    __syncthreads();
    if (tid == 0) {
        float M = sred[0];
        #pragma unroll
        for (int w = 1; w < 8; w++) M = fmaxf(M, sred[w]);
        sM = M;
    }
    __syncthreads();
    const float M = sM;

    // ---- pass 2: sum(exp(psd-M)) + argmin |grid - f_true| ----
    const float ft = f_true[b];
    float se = 0.0f;
    float bd = 1e30f;
    int   bi = NFREQ;
    for (int f = tid; f < NFREQ; f += 256) {
        se += expf(spsd[f] - M);
        const float d = fabsf(grid_f(f) - ft);
        if (d < bd) { bd = d; bi = f; }      // strict <: first occurrence/lane
    }
    #pragma unroll
    for (int o = 16; o > 0; o >>= 1) {
        se += __shfl_down_sync(0xffffffffu, se, o);
        const float od = __shfl_down_sync(0xffffffffu, bd, o);
        const int   oi = __shfl_down_sync(0xffffffffu, bi, o);
        if (od < bd || (od == bd && oi < bi)) { bd = od; bi = oi; }
    }
    __syncthreads();                          // sred reuse
    if ((tid & 31) == 0) {
        const int w = tid >> 5;
        sred[w] = se;
        // pack (dist, idx) ordering into one comparison-friendly pair
        sidx[w] = bi;
        ((volatile float*)sred)[w] = se;      // keep simple: sred=sum
    }
    __shared__ float sbd[8];
    if ((tid & 31) == 0) sbd[tid >> 5] = bd;
    __syncthreads();

    if (tid == 0) {
        float S = 0.0f, fbd = 1e30f;
        int   fbi = NFREQ;
        #pragma unroll
        for (int w = 0; w < 8; w++) {
            S += sred[w];
            if (sbd[w] < fbd || (sbd[w] == fbd && sidx[w] < fbi)) {
                fbd = sbd[w]; fbi = sidx[w];
            }
        }
        const float p = expf(spsd[fbi] - M) / S;    // softmax[idx]
        g_per[b] = -logf(p + 1e-8f);

        __threadfence();
        sticket = (int)atomicAdd(&g_ticket, 1u);
        __threadfence();
    }
    __syncthreads();

    // ---- fused mean: last-arriving block reduces g_per with 64 threads ----
    if (sticket == BATCH - 1) {
        if (tid < BATCH) {
            float v = __ldcg(&g_per[tid]);
            #pragma unroll
            for (int o = 16; o > 0; o >>= 1)
                v += __shfl_down_sync(0xffffffffu, v, o);
            if ((tid & 31) == 0) sred[tid >> 5] = v;
        }
        __syncthreads();
        if (tid == 0) {
            out[0] = (sred[0] + sred[1]) * (1.0f / (float)BATCH);
            g_ticket = 0;                    // self-reset: graph-replay safe
        }
    }
}

// ============================================================================
extern "C" void kernel_launch(void* const* d_in, const int* in_sizes, int n_in,
                              void* d_out, int out_size)
{
    const float* x      = (const float*)d_in[0];   // [64, 1500]
    const float* f_true = (const float*)d_in[1];   // [64]
    const float* fs     = (const float*)d_in[2];   // [64]
    float* out = (float*)d_out;                    // scalar

    dim3 g1(NCHUNKS, BATCH / 2);                   // (20, 32)
    goertzel_kernel<<<g1, 256>>>(x, fs);
    reduce_kernel<<<BATCH, 256>>>(f_true, out);
}